// round 17
// baseline (speedup 1.0000x reference)
#include <cuda_runtime.h>
#include <cuda_fp16.h>
#include <cstdint>

// ---------------- problem constants ----------------
#define Bn   8
#define L1n  7
#define L2n  3
#define N1n  2048
#define N2n  512
#define CINn 512
#define MIDn 256
#define OUTn 512
#define CORn 128
#define Kt   3
#define KMID (Kt*MIDn)   // 768
#define NSL  (L2n*Kt)    // 9
#define KSP  (MIDn+CORn) // 384

__constant__ int c_start[7] = {0,1,2,4,5,7,8};
__constant__ int c_cnt[7]   = {1,1,2,1,2,1,1};

// ---------------- scratch (device globals) ----------------
__device__ float g_tf[(size_t)Bn*L2n*KMID*N2n];      // temporal GEMM out (b,t2,o,n)
__device__ float g_scale[NSL*MIDn];
__device__ float g_shift[NSL*MIDn];
__device__ int   g_idx[(size_t)Bn*L1n*N1n*3];
__device__ float g_w[(size_t)Bn*L1n*N1n*3];
__device__ __align__(16) __half g_P16[(size_t)NSL*Bn*N2n*OUTn];  // P = seedf @ Ws1^T (fp16)
// BN partial sums: slot = ((z*4+bx)*2+half)*KMID + row
__device__ float g_psum[24*4*2*KMID];
__device__ float g_psq[24*4*2*KMID];
// fp16 operands (16B aligned for cp.async)
__device__ __align__(16) __half g_Wt16[KMID*CINn];
__device__ __align__(16) __half g_Ws16[OUTn*KSP];
__device__ __align__(16) __half g_ft16[(size_t)Bn*L2n*N2n*CINn];   // (z,n,c)
__device__ __align__(16) __half g_sf16[(size_t)NSL*Bn*N2n*MIDn];   // seedf (s,b,n,c)
__device__ __align__(16) __half g_of16[(size_t)Bn*L1n*N1n*CORn];   // (z,n,c)

// ===================== PTX helpers (base sm_103-safe) =====================
__device__ __forceinline__ uint32_t smem_u32(const void* p) {
    uint32_t a;
    asm("{ .reg .u64 t; cvta.to.shared.u64 t, %1; cvt.u32.u64 %0, t; }" : "=r"(a) : "l"(p));
    return a;
}
__device__ __forceinline__ void cp16(uint32_t dst, const void* src) {
    asm volatile("cp.async.cg.shared.global [%0], [%1], 16;" :: "r"(dst), "l"(src));
}
__device__ __forceinline__ void ldm4(uint32_t* r, uint32_t addr) {
    asm volatile("ldmatrix.sync.aligned.m8n8.x4.shared.b16 {%0,%1,%2,%3}, [%4];"
                 : "=r"(r[0]), "=r"(r[1]), "=r"(r[2]), "=r"(r[3]) : "r"(addr));
}
__device__ __forceinline__ void mma16816h(float* d, const uint32_t* a, const uint32_t* b) {
    asm volatile("mma.sync.aligned.m16n8k16.row.col.f32.f16.f16.f32 "
                 "{%0,%1,%2,%3}, {%4,%5,%6,%7}, {%8,%9}, {%0,%1,%2,%3};"
                 : "+f"(d[0]), "+f"(d[1]), "+f"(d[2]), "+f"(d[3])
                 : "r"(a[0]), "r"(a[1]), "r"(a[2]), "r"(a[3]), "r"(b[0]), "r"(b[1]));
}

// =====================================================================
// Single-pass fp16 GEMM core. Tile 128x128, BK=32, 256 threads,
// fp32 accumulate, 3-stage cp.async pipeline.
// C[z][m][n] = sum_k A[z][m][k]*B[z][n][k].
// =====================================================================
#define ROWB 80                    // 64B data + 16B pad
#define TILEB (128*ROWB)           // 10240
#define STAGEB (2*TILEB)           // 20480 (A + B)
#define NSTAGE 3
#define GEMM_SMEM (NSTAGE*STAGEB)  // 61440

struct GemmCtx {
    const char *pA, *pB;
    int ldA, ldB;
    int m0, n0;
    uint32_t sbase;
    int tid, lane, wid, wm, wn;
};

__device__ __forceinline__ void gemm_loadTile(const GemmCtx& g, int c, int buf) {
    const int k0 = c << 5;
    const uint32_t sd = g.sbase + buf * STAGEB;
#pragma unroll
    for (int t = 0; t < 4; t++) {
        const int tile = t >> 1;                     // 0 = A, 1 = B
        const int within = ((t & 1) << 8) + g.tid;   // 0..511
        const int row = within >> 2, colB = (within & 3) << 4;
        const char* bp = (tile == 0) ? g.pA : g.pB;
        const int rowg = ((tile == 0) ? g.m0 : g.n0) + row;
        const int ld = (tile == 0) ? g.ldA : g.ldB;
        cp16(sd + tile * TILEB + row * ROWB + colB,
             bp + ((long)rowg * ld + k0) * 2 + colB);
    }
    asm volatile("cp.async.commit_group;" ::: "memory");
}

__device__ __forceinline__ void gemm_computeTile(const GemmCtx& g, int buf,
                                                 float acc[2][8][4]) {
    const uint32_t sA = g.sbase + buf * STAGEB;
    const uint32_t sB = sA + TILEB;
    const int lane = g.lane;
#pragma unroll
    for (int ks = 0; ks < 2; ks++) {
        uint32_t a[2][4], bT[4][4];
        const uint32_t aoff0 = (g.wm + (lane & 15)) * ROWB + ks * 32 + (lane >> 4) * 16;
        ldm4(a[0], sA + aoff0);
        ldm4(a[1], sA + aoff0 + 16 * ROWB);
#pragma unroll
        for (int ib = 0; ib < 4; ib++) {
            const uint32_t row = g.wn + ib * 16 + (lane & 7) + ((lane & 16) ? 8 : 0);
            ldm4(bT[ib], sB + row * ROWB + ks * 32 + ((lane & 8) ? 16 : 0));
        }
#pragma unroll
        for (int im = 0; im < 2; im++)
#pragma unroll
            for (int in = 0; in < 8; in++)
                mma16816h(acc[im][in], a[im], bT[in >> 1] + (in & 1) * 2);
    }
}

__device__ __forceinline__ void gemm_init(GemmCtx& g,
    const __half* A, const __half* B,
    int ldA, int ldB, long strideA, long strideB, void* smem)
{
    const int z = blockIdx.z;
    g.tid = threadIdx.x; g.lane = g.tid & 31; g.wid = g.tid >> 5;
    g.m0 = blockIdx.y * 128; g.n0 = blockIdx.x * 128;
    g.wm = (g.wid & 3) * 32; g.wn = (g.wid >> 2) * 64;
    g.sbase = smem_u32(smem);
    g.pA = (const char*)(A + (long)z * strideA);
    g.pB = (const char*)(B + (long)z * strideB);
    g.ldA = ldA; g.ldB = ldB;
}

// 3-stage mainloop: loads for chunk c+2 issued while computing c; each load
// gets two compute-chunks of shadow. Buffer (c+2)%3 was last read by
// compute(c-1), which all threads completed before this iteration's barrier.
__device__ __forceinline__ void gemm_mainloop(const GemmCtx& g, int Ktot,
                                              float acc[2][8][4]) {
    const int kch = Ktot >> 5;
    gemm_loadTile(g, 0, 0);
    if (kch > 1) gemm_loadTile(g, 1, 1);
    for (int c = 0; c < kch; c++) {
        if (c + 1 < kch)
            asm volatile("cp.async.wait_group 1;" ::: "memory");
        else
            asm volatile("cp.async.wait_group 0;" ::: "memory");
        __syncthreads();
        if (c + 2 < kch) gemm_loadTile(g, c + 2, (c + 2) % NSTAGE);
        gemm_computeTile(g, c % NSTAGE, acc);
    }
}

// ---------------- generic GEMM; fp32 OR fp16 output; optional BN partials ----
__global__ __launch_bounds__(256, 2)
void gemm_mma_kernel(const __half* __restrict__ A,
                     const __half* __restrict__ B,
                     float* __restrict__ C,
                     __half* __restrict__ Ch,
                     int N, int Ktot, int ldA, int ldB,
                     long strideA, long strideB, long strideC,
                     float* __restrict__ psum, float* __restrict__ psq)
{
    extern __shared__ __align__(16) char smem[];
    GemmCtx g;
    gemm_init(g, A, B, ldA, ldB, strideA, strideB, smem);

    float acc[2][8][4];
#pragma unroll
    for (int i = 0; i < 2; i++)
#pragma unroll
        for (int j = 0; j < 8; j++)
#pragma unroll
            for (int q = 0; q < 4; q++) acc[i][j][q] = 0.f;

    gemm_mainloop(g, Ktot, acc);

    if (Ch) {
        __half* cz = Ch + (long)blockIdx.z * strideC;
#pragma unroll
        for (int im = 0; im < 2; im++) {
            const int row = g.m0 + g.wm + im * 16 + (g.lane >> 2);
#pragma unroll
            for (int in = 0; in < 8; in++) {
                const int col = g.n0 + g.wn + in * 8 + (g.lane & 3) * 2;
                *(__half2*)(cz + (long)row * N + col) =
                    __floats2half2_rn(acc[im][in][0], acc[im][in][1]);
                *(__half2*)(cz + (long)(row + 8) * N + col) =
                    __floats2half2_rn(acc[im][in][2], acc[im][in][3]);
            }
        }
    } else {
        float* cz = C + (long)blockIdx.z * strideC;
#pragma unroll
        for (int im = 0; im < 2; im++) {
            const int row = g.m0 + g.wm + im * 16 + (g.lane >> 2);
#pragma unroll
            for (int in = 0; in < 8; in++) {
                const int col = g.n0 + g.wn + in * 8 + (g.lane & 3) * 2;
                *(float2*)(cz + (long)row * N + col) =
                    make_float2(acc[im][in][0], acc[im][in][1]);
                *(float2*)(cz + (long)(row + 8) * N + col) =
                    make_float2(acc[im][in][2], acc[im][in][3]);
            }
        }
    }

    // ---- optional BN partial sums (temporal GEMM only) ----
    if (psum) {
        const int half = g.wid >> 2;
        const long slot = (((long)blockIdx.z * 4 + blockIdx.x) * 2 + half) * KMID;
#pragma unroll
        for (int im = 0; im < 2; im++) {
#pragma unroll
            for (int rr = 0; rr < 2; rr++) {
                float s = 0.f, q = 0.f;
#pragma unroll
                for (int in = 0; in < 8; in++) {
                    const float v0 = acc[im][in][rr * 2];
                    const float v1 = acc[im][in][rr * 2 + 1];
                    s += v0 + v1;
                    q += v0 * v0 + v1 * v1;
                }
                s += __shfl_xor_sync(0xffffffffu, s, 1);
                q += __shfl_xor_sync(0xffffffffu, q, 1);
                s += __shfl_xor_sync(0xffffffffu, s, 2);
                q += __shfl_xor_sync(0xffffffffu, q, 2);
                if ((g.lane & 3) == 0) {
                    const int grow = g.m0 + g.wm + im * 16 + (g.lane >> 2) + rr * 8;
                    psum[slot + grow] = s;
                    psq[slot + grow]  = q;
                }
            }
        }
    }
}

// BN finalize: 2304 channels (t2, o) -> scale/shift
__global__ void bn_finalize_kernel(const float* __restrict__ gamma,
                                   const float* __restrict__ beta)
{
    const int t = blockIdx.x * 256 + threadIdx.x;
    if (t >= L2n * KMID) return;
    const int t2 = t / KMID, o = t % KMID;
    float S = 0.f, Q = 0.f;
    for (int b = 0; b < Bn; b++)
        for (int bx = 0; bx < 4; bx++)
            for (int h = 0; h < 2; h++) {
                const long slot = (((long)(b * 3 + t2) * 4 + bx) * 2 + h) * KMID + o;
                S += g_psum[slot];
                Q += g_psq[slot];
            }
    const float inv = 1.f / (float)(Bn * N2n);
    const float mean = S * inv;
    const float var = Q * inv - mean * mean;
    const float istd = rsqrtf(var + 1e-5f);
    const int k = o >> 8, c = o & 255;
    const int s = t2 * 3 + k;
    const float scl = gamma[c] * istd;
    g_scale[s * MIDn + c] = scl;
    g_shift[s * MIDn + c] = beta[c] - mean * scl;
}

// ---------------- C2 GEMM with fused interp-gather epilogue ----------------
// C[z][outc][n1] = (Ws2 @ ofeat)[outc][n1] + sum_k w_k * P16[idx_k(n1)][outc]
#define SMFP 132   // smem gather-tile pitch in floats (16B multiple)
#define C2_SMEM (128*SMFP*4)   // 67584 >= GEMM_SMEM

__global__ __launch_bounds__(256, 2)
void gemm_c2_fused_kernel(const __half* __restrict__ A,
                          const __half* __restrict__ B,
                          float* __restrict__ C,
                          int N, int Ktot, int ldA, int ldB,
                          long strideA, long strideB, long strideC)
{
    extern __shared__ __align__(16) char smem[];
    GemmCtx g;
    gemm_init(g, A, B, ldA, ldB, strideA, strideB, smem);

    float acc[2][8][4];
#pragma unroll
    for (int i = 0; i < 2; i++)
#pragma unroll
        for (int j = 0; j < 8; j++)
#pragma unroll
            for (int q = 0; q < 4; q++) acc[i][j][q] = 0.f;

    gemm_mainloop(g, Ktot, acc);
    __syncthreads();   // all warps done reading GEMM buffers before smf reuse

    // ---- gather stage: smem as sm[anchor 0..127][outc 0..127] (67.6KB) ----
    const int zz = blockIdx.z;
    const int b = zz / L1n, t1 = zz % L1n;
    float (*smf)[SMFP] = (float(*)[SMFP])smem;
    const int lane = g.lane, wid = g.wid;

#pragma unroll
    for (int aa = 0; aa < 16; aa++) {
        const int a = wid * 16 + aa;
        const long base = ((long)zz * N1n + g.n0 + a) * 3;
        float4 s = make_float4(0.f, 0.f, 0.f, 0.f);
#pragma unroll
        for (int k = 0; k < 3; k++) {
            const int j = g_idx[base + k];
            const float wk = g_w[base + k];
            const int sl = c_start[t1] + (j >> 9);
            const int n = j & 511;
            const uint2 u = *(const uint2*)(g_P16 +
                (((long)sl * Bn + b) * N2n + n) * OUTn + g.m0 + lane * 4);
            const float2 f01 = __half22float2(*(const __half2*)&u.x);
            const float2 f23 = __half22float2(*(const __half2*)&u.y);
            s.x = fmaf(wk, f01.x, s.x);
            s.y = fmaf(wk, f01.y, s.y);
            s.z = fmaf(wk, f23.x, s.z);
            s.w = fmaf(wk, f23.y, s.w);
        }
        *(float4*)(&smf[a][lane * 4]) = s;
    }
    __syncthreads();

    // ---- epilogue: out = acc + gathered interp ----
    float* cz = C + (long)zz * strideC;
#pragma unroll
    for (int im = 0; im < 2; im++) {
        const int rl = g.wm + im * 16 + (lane >> 2);
        const int row = g.m0 + rl;
#pragma unroll
        for (int in = 0; in < 8; in++) {
            const int cl = g.wn + in * 8 + (lane & 3) * 2;
            const int col = g.n0 + cl;
            *(float2*)(cz + (long)row * N + col) = make_float2(
                acc[im][in][0] + smf[cl][rl],
                acc[im][in][1] + smf[cl + 1][rl]);
            *(float2*)(cz + (long)(row + 8) * N + col) = make_float2(
                acc[im][in][2] + smf[cl][rl + 8],
                acc[im][in][3] + smf[cl + 1][rl + 8]);
        }
    }
}

// =====================================================================
// prep kernels (fp32 -> fp16)
// =====================================================================
__global__ void cvt_kernel(const float* __restrict__ src,
                           __half* __restrict__ dst, long n)
{
    const long i = (long)blockIdx.x * 256 + threadIdx.x;
    if (i < n) dst[i] = __float2half(src[i]);
}

// features (z,c=512,n=512) -> g_ft16 (z,n,c)
__global__ void featT_kernel(const float* __restrict__ feat)
{
    __shared__ float sm[32][33];
    const int z = blockIdx.z, n0 = blockIdx.x * 32, c0 = blockIdx.y * 32;
    const int tx = threadIdx.x & 31, ty = threadIdx.x >> 5;
    const float* src = feat + (long)z * CINn * N2n;
#pragma unroll
    for (int i = 0; i < 4; i++)
        sm[ty + i * 8][tx] = src[(long)(c0 + ty + i * 8) * N2n + n0 + tx];
    __syncthreads();
#pragma unroll
    for (int i = 0; i < 4; i++) {
        const int n = n0 + ty + i * 8;
        g_ft16[((long)z * N2n + n) * CINn + c0 + tx] = __float2half(sm[tx][ty + i * 8]);
    }
}

// original_features (z,c=128,n=2048) -> g_of16 (z,n,c)
__global__ void ofeatT_kernel(const float* __restrict__ ofeat)
{
    __shared__ float sm[32][33];
    const int z = blockIdx.z, n0 = blockIdx.x * 32, c0 = blockIdx.y * 32;
    const int tx = threadIdx.x & 31, ty = threadIdx.x >> 5;
    const float* src = ofeat + (long)z * CORn * N1n;
#pragma unroll
    for (int i = 0; i < 4; i++)
        sm[ty + i * 8][tx] = src[(long)(c0 + ty + i * 8) * N1n + n0 + tx];
    __syncthreads();
#pragma unroll
    for (int i = 0; i < 4; i++) {
        const int n = n0 + ty + i * 8;
        g_of16[((long)z * N1n + n) * CORn + c0 + tx] = __float2half(sm[tx][ty + i * 8]);
    }
}

// BN apply + ReLU + transpose: g_tf (b,t2,o,n) -> g_sf16 (s,b,n,c)
__global__ void bn_transpose_kernel()
{
    __shared__ float sm[32][33];
    const int s = blockIdx.z >> 3, b = blockIdx.z & 7;
    const int t2 = s / 3, k = s % 3;
    const int n0 = blockIdx.x * 32, c0 = blockIdx.y * 32;
    const int tx = threadIdx.x & 31, ty = threadIdx.x >> 5;

    const float* src = g_tf + ((long)(b * L2n + t2) * KMID + k * MIDn) * N2n;
#pragma unroll
    for (int i = 0; i < 4; i++) {
        const int cl = ty + i * 8;
        const int c = c0 + cl;
        float v = src[(long)c * N2n + n0 + tx];
        v = fmaxf(fmaf(v, g_scale[s * MIDn + c], g_shift[s * MIDn + c]), 0.f);
        sm[cl][tx] = v;
    }
    __syncthreads();
    const long base = (long)blockIdx.z * N2n * MIDn;
#pragma unroll
    for (int i = 0; i < 4; i++) {
        const int n = n0 + ty + i * 8;
        g_sf16[base + (long)n * MIDn + c0 + tx] = __float2half(sm[tx][ty + i * 8]);
    }
}

// =====================================================================
// 3-NN: 512 threads, two halves split the neighbor list, sorted-top3
// merge replays candidates in scan order (bit-identical to full scan).
// =====================================================================
__global__ __launch_bounds__(512)
void knn_kernel(const float* __restrict__ oxyz,
                const float* __restrict__ xyzs)
{
    const int zz = blockIdx.y;
    const int b = zz / L1n, t1 = zz % L1n;
    const int M = c_cnt[t1] * N2n;

    __shared__ float4 nb[1024];
    __shared__ float sd[2][256][3];
    __shared__ int   si[2][256][3];

    for (int j = threadIdx.x; j < M; j += 512) {
        const int sl = c_start[t1] + (j >> 9);
        const int t2 = sl / 3;
        const int n = j & 511;
        const float* p = xyzs + (((long)b * L2n + t2) * N2n + n) * 3;
        const float x = p[0], y = p[1], zc = p[2];
        nb[j] = make_float4(x, y, zc, x * x + y * y + zc * zc);
    }
    __syncthreads();

    const int la = threadIdx.x & 255;
    const int half = threadIdx.x >> 8;
    const int n1 = blockIdx.x * 256 + la;
    const float* a = oxyz + (((long)b * L1n + t1) * N1n + n1) * 3;
    const float ax = a[0], ay = a[1], az = a[2];
    const float an = ax * ax + ay * ay + az * az;

    const int jb = half * (M >> 1), je = jb + (M >> 1);
    float d0 = 1e30f, d1 = 1e30f, d2 = 1e30f;
    int i0 = 0, i1 = 0, i2 = 0;
    for (int j = jb; j < je; j++) {
        const float4 q = nb[j];
        const float d = an + q.w - 2.f * (ax * q.x + ay * q.y + az * q.z);
        if (d < d2) {
            if (d < d1) {
                d2 = d1; i2 = i1;
                if (d < d0) { d1 = d0; i1 = i0; d0 = d; i0 = j; }
                else        { d1 = d;  i1 = j; }
            } else { d2 = d; i2 = j; }
        }
    }
    sd[half][la][0] = d0; sd[half][la][1] = d1; sd[half][la][2] = d2;
    si[half][la][0] = i0; si[half][la][1] = i1; si[half][la][2] = i2;
    __syncthreads();

    if (half == 0) {
        float e0 = 1e30f, e1 = 1e30f, e2 = 1e30f;
        int j0 = 0, j1 = 0, j2 = 0;
#pragma unroll
        for (int h = 0; h < 2; h++)
#pragma unroll
            for (int k = 0; k < 3; k++) {
                const float d = sd[h][la][k];
                const int   j = si[h][la][k];
                if (d < e2) {
                    if (d < e1) {
                        e2 = e1; j2 = j1;
                        if (d < e0) { e1 = e0; j1 = j0; e0 = d; j0 = j; }
                        else        { e1 = d;  j1 = j; }
                    } else { e2 = d; j2 = j; }
                }
            }
        const float s0 = sqrtf(fmaxf(e0, 1e-12f));
        const float s1 = sqrtf(fmaxf(e1, 1e-12f));
        const float s2 = sqrtf(fmaxf(e2, 1e-12f));
        float w0 = 1.f / (s0 + 1e-8f);
        float w1 = 1.f / (s1 + 1e-8f);
        float w2 = 1.f / (s2 + 1e-8f);
        const float inv = 1.f / (w0 + w1 + w2);
        const long base = ((long)zz * N1n + n1) * 3;
        g_idx[base] = j0; g_idx[base + 1] = j1; g_idx[base + 2] = j2;
        g_w[base] = w0 * inv; g_w[base + 1] = w1 * inv; g_w[base + 2] = w2 * inv;
    }
}

// =====================================================================
// launch — two-stream orchestration (capture-safe fork/join via events)
// =====================================================================
extern "C" void kernel_launch(void* const* d_in, const int* in_sizes, int n_in,
                              void* d_out, int out_size)
{
    const float* xyzs  = (const float*)d_in[0];
    const float* oxyz  = (const float*)d_in[1];
    const float* feat  = (const float*)d_in[2];
    const float* ofeat = (const float*)d_in[3];
    const float* Wt    = (const float*)d_in[4];
    const float* gamma = (const float*)d_in[5];
    const float* beta  = (const float*)d_in[6];
    const float* Ws    = (const float*)d_in[7];
    float* out = (float*)d_out;

    static cudaStream_t s1 = nullptr;
    static cudaEvent_t evFork = nullptr, evJoin = nullptr;
    if (!s1) {
        cudaStreamCreateWithFlags(&s1, cudaStreamNonBlocking);
        cudaEventCreateWithFlags(&evFork, cudaEventDisableTiming);
        cudaEventCreateWithFlags(&evJoin, cudaEventDisableTiming);
    }

    cudaFuncSetAttribute(gemm_mma_kernel,
                         cudaFuncAttributeMaxDynamicSharedMemorySize, GEMM_SMEM);
    cudaFuncSetAttribute(gemm_c2_fused_kernel,
                         cudaFuncAttributeMaxDynamicSharedMemorySize, C2_SMEM);

    float *p_tf, *p_psum, *p_psq;
    __half *p_P16, *pWt16, *pWs16, *pFt16, *pSf16, *pOf16;
    cudaGetSymbolAddress((void**)&p_tf,  g_tf);
    cudaGetSymbolAddress((void**)&p_P16, g_P16);
    cudaGetSymbolAddress((void**)&p_psum, g_psum);
    cudaGetSymbolAddress((void**)&p_psq,  g_psq);
    cudaGetSymbolAddress((void**)&pWt16, g_Wt16);
    cudaGetSymbolAddress((void**)&pWs16, g_Ws16);
    cudaGetSymbolAddress((void**)&pFt16, g_ft16);
    cudaGetSymbolAddress((void**)&pSf16, g_sf16);
    cudaGetSymbolAddress((void**)&pOf16, g_of16);

    const long nf_elems = (long)Bn * L1n * OUTn * N1n;
    float* out_nf = out;

    // ---- fork side stream ----
    cudaEventRecord(evFork, 0);
    cudaStreamWaitEvent(s1, evFork, 0);

    // ---- side stream (chain 2): xyz copy, Ws cvt, ofeat transpose, 3-NN ----
    if ((long)out_size > nf_elems) {
        const long off = (long)out_size - nf_elems;   // original_xyzs first
        cudaMemcpyAsync(out, oxyz, off * sizeof(float),
                        cudaMemcpyDeviceToDevice, s1);
        out_nf = out + off;
    }
    cvt_kernel<<<(OUTn * KSP + 255) / 256, 256, 0, s1>>>(Ws, pWs16, (long)OUTn * KSP);
    {
        dim3 grid(N1n / 32, CORn / 32, Bn * L1n);
        ofeatT_kernel<<<grid, 256, 0, s1>>>(ofeat);
    }
    {
        dim3 grid(N1n / 256, Bn * L1n);
        knn_kernel<<<grid, 512, 0, s1>>>(oxyz, xyzs);
    }
    cudaEventRecord(evJoin, s1);

    // ---- main stream (chain 1) ----
    cvt_kernel<<<(KMID * CINn + 255) / 256, 256>>>(Wt, pWt16, (long)KMID * CINn);
    {
        dim3 grid(N2n / 32, CINn / 32, Bn * L2n);
        featT_kernel<<<grid, 256>>>(feat);
    }
    // temporal GEMM (+ BN partial sums): A=Wt(768x512), B=g_ft per z -> g_tf (fp32)
    {
        dim3 grid(N2n / 128, KMID / 128, Bn * L2n);
        gemm_mma_kernel<<<grid, 256, GEMM_SMEM>>>(pWt16, pFt16, p_tf, nullptr,
            N2n, CINn, CINn, CINn,
            0L, (long)N2n * CINn, (long)KMID * N2n,
            p_psum, p_psq);
    }
    // BN finalize + apply/transpose
    bn_finalize_kernel<<<(L2n * KMID + 255) / 256, 256>>>(gamma, beta);
    {
        dim3 grid(N2n / 32, MIDn / 32, NSL * Bn);
        bn_transpose_kernel<<<grid, 256>>>();
    }

    // ---- join: P-GEMM needs Ws; C2 needs ofeat/knn too ----
    cudaStreamWaitEvent(0, evJoin, 0);

    // P-GEMM: A=seedf per z(512x256), B=Ws1(512 rows, k=0..255, ld=384) -> g_P16 (fp16)
    {
        dim3 grid(OUTn / 128, N2n / 128, NSL * Bn);
        gemm_mma_kernel<<<grid, 256, GEMM_SMEM>>>(pSf16, pWs16, nullptr, p_P16,
            OUTn, MIDn, MIDn, KSP,
            (long)N2n * MIDn, 0L, (long)N2n * OUTn,
            nullptr, nullptr);
    }
    // C2-GEMM + fused gather: out = Ws2@ofeat + interp(P16)
    {
        dim3 grid(N1n / 128, OUTn / 128, Bn * L1n);
        gemm_c2_fused_kernel<<<grid, 256, C2_SMEM>>>(pWs16 + MIDn,
            pOf16, out_nf,
            N1n, CORn, KSP, CORn,
            0L, (long)N1n * CORn, (long)OUTn * N1n);
    }
}